// round 4
// baseline (speedup 1.0000x reference)
#include <cuda_runtime.h>

#define VOCAB 200000
#define EMBED 128
#define N_POS 10
#define N_NEG 64
#define N_ROWS (1 + N_POS + N_NEG)   // 75

// Scratch: index of the single nonzero in each one-hot row.
// slot 0 = center, slots 1..10 = positives, slots 11..74 = negatives.
__device__ int g_idx[N_ROWS];

// ---------------------------------------------------------------------------
// Kernel 1: scan the one-hot rows, record the nonzero index per row.
// Exactly one element per row is nonzero (exact 1.0f from jax.nn.one_hot),
// so exactly one thread writes each slot -> deterministic, no init needed.
// grid = (ceil(VOCAB/1024), 75), block = 256, float4 per thread.
// ---------------------------------------------------------------------------
__global__ void __launch_bounds__(256)
find_indices_kernel(const float* __restrict__ center,
                    const float* __restrict__ pos,
                    const float* __restrict__ neg)
{
    const int row = blockIdx.y;
    const float* base;
    if (row == 0)            base = center;
    else if (row <= N_POS)   base = pos + (size_t)(row - 1) * VOCAB;
    else                     base = neg + (size_t)(row - 1 - N_POS) * VOCAB;

    int i = (blockIdx.x * blockDim.x + threadIdx.x) * 4;
    if (i < VOCAB) {  // VOCAB % 4 == 0, so full float4 is in bounds
        float4 v = *reinterpret_cast<const float4*>(base + i);
        if (v.x != 0.0f) g_idx[row] = i + 0;
        if (v.y != 0.0f) g_idx[row] = i + 1;
        if (v.z != 0.0f) g_idx[row] = i + 2;
        if (v.w != 0.0f) g_idx[row] = i + 3;
    }
}

// ---------------------------------------------------------------------------
// Kernel 2: gather embeddings, compute 74 dot products + log-sigmoid sum.
// One block, 1024 threads = 32 warps. Warp w handles scores w, w+32, w+64.
// score s in [0,10):  dot(ctr, input_emb[:, g_idx[1+s]])   (column gather)
// score s in [10,74): dot(ctr, output_emb[g_idx[1+s], :])  (row gather)
// Deterministic reduction: per-warp partials -> smem -> thread 0 serial sum.
// ---------------------------------------------------------------------------
__device__ __forceinline__ float log_sigmoid(float x) {
    // numerically stable: min(x,0) - log1p(exp(-|x|))
    return fminf(x, 0.0f) - log1pf(__expf(-fabsf(x)));
}

__global__ void __launch_bounds__(1024)
score_kernel(const float* __restrict__ in_emb,   // [EMBED, VOCAB]
             const float* __restrict__ out_emb,  // [VOCAB, EMBED]
             float* __restrict__ out)
{
    __shared__ float ctr[EMBED];
    __shared__ float warp_sum[32];

    const int tid  = threadIdx.x;
    const int warp = tid >> 5;
    const int lane = tid & 31;

    const int c = g_idx[0];
    if (tid < EMBED)
        ctr[tid] = in_emb[(size_t)tid * VOCAB + c];
    __syncthreads();

    float local = 0.0f;
    #pragma unroll
    for (int s = warp; s < N_POS + N_NEG; s += 32) {
        const int idx = g_idx[s + 1];
        float dot = 0.0f;
        if (s < N_POS) {
            #pragma unroll
            for (int k = lane; k < EMBED; k += 32)
                dot = fmaf(ctr[k], in_emb[(size_t)k * VOCAB + idx], dot);
        } else {
            #pragma unroll
            for (int k = lane; k < EMBED; k += 32)
                dot = fmaf(ctr[k], out_emb[(size_t)idx * EMBED + k], dot);
        }
        #pragma unroll
        for (int o = 16; o; o >>= 1)
            dot += __shfl_xor_sync(0xFFFFFFFFu, dot, o);
        if (lane == 0) {
            const float x = (s < N_POS) ? dot : -dot;
            local += log_sigmoid(x);
        }
    }

    if (lane == 0) warp_sum[warp] = local;
    __syncthreads();

    if (tid == 0) {
        float acc = 0.0f;
        #pragma unroll
        for (int w = 0; w < 32; w++) acc += warp_sum[w];
        out[0] = -acc;
    }
}

// ---------------------------------------------------------------------------
// Launch. Inputs (metadata order):
//   d_in[0] center_word        [200000]        f32
//   d_in[1] positive_words     [10, 200000]    f32
//   d_in[2] negative_words     [64, 200000]    f32
//   d_in[3] input_embeddings   [128, 200000]   f32
//   d_in[4] output_embeddings  [200000, 128]   f32
// d_out: 1 x f32 (scalar loss)
// ---------------------------------------------------------------------------
extern "C" void kernel_launch(void* const* d_in, const int* in_sizes, int n_in,
                              void* d_out, int out_size)
{
    const float* center = (const float*)d_in[0];
    const float* pos    = (const float*)d_in[1];
    const float* neg    = (const float*)d_in[2];
    const float* in_emb = (const float*)d_in[3];
    const float* ot_emb = (const float*)d_in[4];
    float* out          = (float*)d_out;

    // 256 threads x 4 floats = 1024 elems per block; ceil(200000/1024) = 196
    dim3 grid1((VOCAB + 1023) / 1024, N_ROWS);
    find_indices_kernel<<<grid1, 256>>>(center, pos, neg);

    score_kernel<<<1, 1024>>>(in_emb, ot_emb, out);
}